// round 5
// baseline (speedup 1.0000x reference)
#include <cuda_runtime.h>

#define N_NODES     100000
#define IN_DIM      128
#define NUM_ET      16
#define E_PER_TYPE  100000
#define N_EDGES     (NUM_ET * E_PER_TYPE)   // 1,600,000

// One warp per edge.
//   - lanes 0/1 fetch src/dst (int32 — JAX x64 is disabled, "int64" downgrades) and broadcast
//   - each lane loads float4 of z[src], z[dst], weight[t]  (contiguous 512B/row per warp)
//   - weighted dot -> warp shuffle reduction -> sigmoid
//   - lane 0 writes out[e] (per_type) and, if it fits, out[N_EDGES + e] (score)
__global__ __launch_bounds__(256)
void mipd_kernel(const float* __restrict__ z,
                 const float* __restrict__ w,
                 const int*   __restrict__ ei,
                 float* __restrict__ out,
                 int out_size)
{
    const int gwarp = (blockIdx.x * 256 + threadIdx.x) >> 5;
    const int lane  = threadIdx.x & 31;
    if (gwarp >= N_EDGES) return;

    const int t = gwarp / E_PER_TYPE;          // compiler -> magic-multiply
    const int i = gwarp - t * E_PER_TYPE;

    // edge_index layout: (NUM_ET, 2, E_PER_TYPE) int32
    int idx32 = 0;
    if (lane < 2) {
        idx32 = ei[t * (2 * E_PER_TYPE) + lane * E_PER_TYPE + i];
    }
    const int src = __shfl_sync(0xffffffffu, idx32, 0);
    const int dst = __shfl_sync(0xffffffffu, idx32, 1);

    const float4 a  = *(const float4*)(z + (size_t)src * IN_DIM + lane * 4);
    const float4 b  = *(const float4*)(z + (size_t)dst * IN_DIM + lane * 4);
    const float4 ww = *(const float4*)(w + (size_t)t   * IN_DIM + lane * 4);

    float s = a.x * b.x * ww.x;
    s = fmaf(a.y * b.y, ww.y, s);
    s = fmaf(a.z * b.z, ww.z, s);
    s = fmaf(a.w * b.w, ww.w, s);

    #pragma unroll
    for (int off = 16; off > 0; off >>= 1)
        s += __shfl_xor_sync(0xffffffffu, s, off);

    if (lane == 0) {
        const float v = 1.0f / (1.0f + expf(-s));
        out[gwarp] = v;                             // per_type (16,100000) row-major
        if (out_size >= 2 * N_EDGES)
            out[N_EDGES + gwarp] = v;               // score = same values, reshape(-1)
    }
}

extern "C" void kernel_launch(void* const* d_in, const int* in_sizes, int n_in,
                              void* d_out, int out_size)
{
    const float* z  = (const float*)d_in[0];        // (100000, 128) fp32
    const float* w  = (const float*)d_in[1];        // (16, 128) fp32
    const int*   ei = (const int*)d_in[2];          // (16, 2, 100000) int32
    float*       out = (float*)d_out;

    const int threads = 256;
    const long long total_threads = (long long)N_EDGES * 32;
    const int blocks = (int)((total_threads + threads - 1) / threads);  // 200000
    mipd_kernel<<<blocks, threads>>>(z, w, ei, out, out_size);
}

// round 6
// speedup vs baseline: 2.2449x; 2.2449x over previous
#include <cuda_runtime.h>
#include <cuda_fp16.h>

#define N_NODES     100000
#define IN_DIM      128
#define NUM_ET      16
#define E_PER_TYPE  100000
#define N_EDGES     (NUM_ET * E_PER_TYPE)   // 1,600,000

#define CHUNK            800
#define BLOCKS_PER_TYPE  125      // 125 * 800 = 100000 edges per type
#define ITERS            25       // 25 iters * 32 edges/block-iter = 800

// fp16 copy of z (25.6 MB scratch — static __device__, no allocation)
__device__ __align__(16) __half g_zh[N_NODES * IN_DIM];

// ---------------- conversion: z fp32 -> fp16 ----------------
__global__ __launch_bounds__(256)
void convert_z_kernel(const float* __restrict__ z)
{
    const int i = blockIdx.x * blockDim.x + threadIdx.x;  // 8 floats per thread
    if (i >= N_NODES * IN_DIM / 8) return;
    const float4 v0 = ((const float4*)z)[2 * i];
    const float4 v1 = ((const float4*)z)[2 * i + 1];
    __half2 h0 = __floats2half2_rn(v0.x, v0.y);
    __half2 h1 = __floats2half2_rn(v0.z, v0.w);
    __half2 h2 = __floats2half2_rn(v1.x, v1.y);
    __half2 h3 = __floats2half2_rn(v1.z, v1.w);
    uint4 o;
    o.x = *(unsigned*)&h0; o.y = *(unsigned*)&h1;
    o.z = *(unsigned*)&h2; o.w = *(unsigned*)&h3;
    ((uint4*)g_zh)[i] = o;
}

// accumulate 8 dims: fp16 elementwise product, fp32 weighted accumulate
__device__ __forceinline__ float dot8(uint4 a, uint4 b, float4 w0, float4 w1, float s)
{
    const __half2* ha = (const __half2*)&a;
    const __half2* hb = (const __half2*)&b;
    __half2 p0 = __hmul2(ha[0], hb[0]);
    __half2 p1 = __hmul2(ha[1], hb[1]);
    __half2 p2 = __hmul2(ha[2], hb[2]);
    __half2 p3 = __hmul2(ha[3], hb[3]);
    float2 f0 = __half22float2(p0);
    float2 f1 = __half22float2(p1);
    float2 f2 = __half22float2(p2);
    float2 f3 = __half22float2(p3);
    s = fmaf(f0.x, w0.x, s); s = fmaf(f0.y, w0.y, s);
    s = fmaf(f1.x, w0.z, s); s = fmaf(f1.y, w0.w, s);
    s = fmaf(f2.x, w1.x, s); s = fmaf(f2.y, w1.y, s);
    s = fmaf(f3.x, w1.z, s); s = fmaf(f3.y, w1.w, s);
    return s;
}

// ---------------- main: 8 lanes per edge, 4 edges per warp ----------------
// Block owns one edge-type chunk of 800 edges; w[t] lives in registers.
__global__ __launch_bounds__(256)
void mipd_f16_kernel(const float* __restrict__ w,
                     const int*   __restrict__ ei,
                     float* __restrict__ out)
{
    const int warp = threadIdx.x >> 5;       // 0..7
    const int lane = threadIdx.x & 31;
    const int q    = lane >> 3;              // quarter-warp = edge slot 0..3
    const int l    = lane & 7;               // lane within edge

    const int t           = blockIdx.x / BLOCKS_PER_TYPE;
    const int chunk       = blockIdx.x - t * BLOCKS_PER_TYPE;
    const int chunk_start = chunk * CHUNK;

    // this thread's 16 weight values (dims l*16 .. l*16+15), held for all 25 iters
    const float* wrow = w + t * IN_DIM + l * 16;
    const float4 w0 = ((const float4*)wrow)[0];
    const float4 w1 = ((const float4*)wrow)[1];
    const float4 w2 = ((const float4*)wrow)[2];
    const float4 w3 = ((const float4*)wrow)[3];

    const int* ei_t = ei + t * (2 * E_PER_TYPE);

    for (int it = 0; it < ITERS; ++it) {
        const int i_base = chunk_start + it * 32 + warp * 4;  // first of 4 edges (within type)

        // lanes 0-3 load src[i_base+0..3], lanes 4-7 load dst[i_base+0..3]
        int idxv = 0;
        if (lane < 8)
            idxv = ei_t[(lane >> 2) * E_PER_TYPE + i_base + (lane & 3)];
        const int src = __shfl_sync(0xffffffffu, idxv, q);
        const int dst = __shfl_sync(0xffffffffu, idxv, 4 + q);

        // each lane covers 16 dims = 32B fp16 of each row
        const __half* arow = g_zh + (size_t)src * IN_DIM + l * 16;
        const __half* brow = g_zh + (size_t)dst * IN_DIM + l * 16;
        const uint4 a0 = *(const uint4*)(arow);
        const uint4 a1 = *(const uint4*)(arow + 8);
        const uint4 b0 = *(const uint4*)(brow);
        const uint4 b1 = *(const uint4*)(brow + 8);

        float s = 0.0f;
        s = dot8(a0, b0, w0, w1, s);
        s = dot8(a1, b1, w2, w3, s);

        // reduce across the 8 lanes of this edge (xor stays inside the octet)
        #pragma unroll
        for (int off = 4; off > 0; off >>= 1)
            s += __shfl_xor_sync(0xffffffffu, s, off);

        if (l == 0) {
            const float v = 1.0f / (1.0f + __expf(-s));
            const int g = t * E_PER_TYPE + i_base + q;   // lanes 0,8,16,24 -> consecutive g
            out[g]           = v;                        // per_type
            out[N_EDGES + g] = v;                        // score (same values flattened)
        }
    }
}

extern "C" void kernel_launch(void* const* d_in, const int* in_sizes, int n_in,
                              void* d_out, int out_size)
{
    const float* z  = (const float*)d_in[0];   // (100000, 128) fp32
    const float* w  = (const float*)d_in[1];   // (16, 128) fp32
    const int*   ei = (const int*)d_in[2];     // (16, 2, 100000) int32
    float*       out = (float*)d_out;          // 3,200,000 fp32

    // 1) stage z as fp16
    const int conv_threads = N_NODES * IN_DIM / 8;     // 1.6M
    convert_z_kernel<<<(conv_threads + 255) / 256, 256>>>(z);

    // 2) decode: 16 types * 125 chunks = 2000 blocks
    mipd_f16_kernel<<<NUM_ET * BLOCKS_PER_TYPE, 256>>>(w, ei, out);
}

// round 7
// speedup vs baseline: 2.7266x; 1.2146x over previous
#include <cuda_runtime.h>
#include <cuda_fp16.h>

#define N_NODES     100000
#define IN_DIM      128
#define NUM_ET      16
#define E_PER_TYPE  100000
#define N_EDGES     (NUM_ET * E_PER_TYPE)   // 1,600,000

#define CHUNK            160
#define BLOCKS_PER_TYPE  625      // 625 * 160 = 100000 edges per type
#define ITERS            5        // 5 iters * 32 edges/block-iter = 160

// fp16 copy of z (25.6 MB scratch — static __device__, no allocation)
__device__ __align__(16) __half g_zh[N_NODES * IN_DIM];

// ---------------- conversion: z fp32 -> fp16 ----------------
__global__ __launch_bounds__(256)
void convert_z_kernel(const float* __restrict__ z)
{
    const int i = blockIdx.x * blockDim.x + threadIdx.x;  // 8 floats per thread
    if (i >= N_NODES * IN_DIM / 8) return;
    const float4 v0 = ((const float4*)z)[2 * i];
    const float4 v1 = ((const float4*)z)[2 * i + 1];
    __half2 h0 = __floats2half2_rn(v0.x, v0.y);
    __half2 h1 = __floats2half2_rn(v0.z, v0.w);
    __half2 h2 = __floats2half2_rn(v1.x, v1.y);
    __half2 h3 = __floats2half2_rn(v1.z, v1.w);
    uint4 o;
    o.x = *(unsigned*)&h0; o.y = *(unsigned*)&h1;
    o.z = *(unsigned*)&h2; o.w = *(unsigned*)&h3;
    ((uint4*)g_zh)[i] = o;
}

// accumulate 8 dims: fp16 elementwise product, fp32 weighted accumulate
__device__ __forceinline__ float dot8(uint4 a, uint4 b, float4 w0, float4 w1, float s)
{
    const __half2* ha = (const __half2*)&a;
    const __half2* hb = (const __half2*)&b;
    __half2 p0 = __hmul2(ha[0], hb[0]);
    __half2 p1 = __hmul2(ha[1], hb[1]);
    __half2 p2 = __hmul2(ha[2], hb[2]);
    __half2 p3 = __hmul2(ha[3], hb[3]);
    float2 f0 = __half22float2(p0);
    float2 f1 = __half22float2(p1);
    float2 f2 = __half22float2(p2);
    float2 f3 = __half22float2(p3);
    s = fmaf(f0.x, w0.x, s); s = fmaf(f0.y, w0.y, s);
    s = fmaf(f1.x, w0.z, s); s = fmaf(f1.y, w0.w, s);
    s = fmaf(f2.x, w1.x, s); s = fmaf(f2.y, w1.y, s);
    s = fmaf(f3.x, w1.z, s); s = fmaf(f3.y, w1.w, s);
    return s;
}

// ---------------- main: 8 lanes per edge, 4 edges per warp ----------------
// Lane l covers dims [8l, 8l+8) and [64+8l, 64+8l+8): each uint4 load's 8 lanes
// form ONE contiguous 128B line of the fp16 row -> 4 wavefronts per edge (minimum).
__global__ __launch_bounds__(256)
void mipd_f16_kernel(const float* __restrict__ w,
                     const int*   __restrict__ ei,
                     float* __restrict__ out)
{
    const int warp = threadIdx.x >> 5;       // 0..7
    const int lane = threadIdx.x & 31;
    const int q    = lane >> 3;              // quarter-warp = edge slot 0..3
    const int l    = lane & 7;               // lane within edge

    const int t           = blockIdx.x / BLOCKS_PER_TYPE;
    const int chunk       = blockIdx.x - t * BLOCKS_PER_TYPE;
    const int chunk_start = chunk * CHUNK;

    // weights for dims [8l,8l+8) and [64+8l,64+8l+8), held in regs for all iters
    const float* wrow = w + t * IN_DIM;
    const float4 w0 = *(const float4*)(wrow + 8 * l);
    const float4 w1 = *(const float4*)(wrow + 8 * l + 4);
    const float4 w2 = *(const float4*)(wrow + 64 + 8 * l);
    const float4 w3 = *(const float4*)(wrow + 64 + 8 * l + 4);

    const int* ei_t = ei + t * (2 * E_PER_TYPE);

    for (int it = 0; it < ITERS; ++it) {
        const int i_base = chunk_start + it * 32 + warp * 4;  // first of 4 edges (within type)

        // lanes 0-3 load src[i_base+0..3], lanes 4-7 load dst[i_base+0..3]
        int idxv = 0;
        if (lane < 8)
            idxv = ei_t[(lane >> 2) * E_PER_TYPE + i_base + (lane & 3)];
        const int src = __shfl_sync(0xffffffffu, idxv, q);
        const int dst = __shfl_sync(0xffffffffu, idxv, 4 + q);

        const __half* arow = g_zh + (size_t)src * IN_DIM;
        const __half* brow = g_zh + (size_t)dst * IN_DIM;
        // line 0: halves [8l, 8l+8)   line 1: halves [64+8l, 64+8l+8)
        const uint4 a0 = *(const uint4*)(arow + 8 * l);
        const uint4 a1 = *(const uint4*)(arow + 64 + 8 * l);
        const uint4 b0 = *(const uint4*)(brow + 8 * l);
        const uint4 b1 = *(const uint4*)(brow + 64 + 8 * l);

        float s = 0.0f;
        s = dot8(a0, b0, w0, w1, s);
        s = dot8(a1, b1, w2, w3, s);

        // reduce across the 8 lanes of this edge (xor stays inside the octet)
        #pragma unroll
        for (int off = 4; off > 0; off >>= 1)
            s += __shfl_xor_sync(0xffffffffu, s, off);

        if (l == 0) {
            const float v = 1.0f / (1.0f + __expf(-s));
            const int g = t * E_PER_TYPE + i_base + q;   // lanes 0,8,16,24 -> consecutive g
            out[g]           = v;                        // per_type
            out[N_EDGES + g] = v;                        // score (same values flattened)
        }
    }
}

extern "C" void kernel_launch(void* const* d_in, const int* in_sizes, int n_in,
                              void* d_out, int out_size)
{
    const float* z  = (const float*)d_in[0];   // (100000, 128) fp32
    const float* w  = (const float*)d_in[1];   // (16, 128) fp32
    const int*   ei = (const int*)d_in[2];     // (16, 2, 100000) int32
    float*       out = (float*)d_out;          // 3,200,000 fp32

    // 1) stage z as fp16
    const int conv_threads = N_NODES * IN_DIM / 8;     // 1.6M
    convert_z_kernel<<<(conv_threads + 255) / 256, 256>>>(z);

    // 2) decode: 16 types * 625 chunks = 10000 blocks
    mipd_f16_kernel<<<NUM_ET * BLOCKS_PER_TYPE, 256>>>(w, ei, out);
}